// round 17
// baseline (speedup 1.0000x reference)
#include <cuda_runtime.h>
#include <cuda_fp16.h>
#include <cstdint>

#define N_NODES 50000
#define N_EDGES 600000
#define IN_DIM  128
#define HID     256

#define SCAN_B  1024
#define NBLK    ((N_NODES + SCAN_B - 1) / SCAN_B)   // 49

// ---------------- device scratch (no allocation allowed) ----------------
__device__ int    g_count[N_NODES];
__device__ int    g_fill[N_NODES];
__device__ int    g_rowptr[N_NODES + 1];
__device__ int    g_bsum[NBLK];
__device__ int    g_boff[NBLK];
__device__ int    g_ticket;          // zero-initialized; reset after each use
__device__ float  g_dinv[N_NODES];
__device__ int    g_col[N_EDGES];
__device__ __half g_x16[(size_t)N_NODES * IN_DIM];     // x in fp16
__device__ __half g_w1t[256 * 128];                    // W1^T fp16 [n][k]
__device__ __half g_w2t[256 * 256];                    // W2^T fp16 [n][k]
__device__ __half g_h1h[(size_t)N_NODES * HID];        // h1 fp16

// ---------------- preprocessing ----------------
__global__ void k_init(const float* __restrict__ x, const float* __restrict__ W1,
                       const float* __restrict__ W2) {
    int i = blockIdx.x * blockDim.x + threadIdx.x;
    if (i < N_NODES) { g_count[i] = 0; g_fill[i] = 0; }
    if (i < N_NODES * IN_DIM / 4) {
        float4 v = ((const float4*)x)[i];
        __half2 h0 = __floats2half2_rn(v.x, v.y);
        __half2 h1 = __floats2half2_rn(v.z, v.w);
        uint2 u;
        u.x = *(const uint32_t*)&h0;
        u.y = *(const uint32_t*)&h1;
        ((uint2*)g_x16)[i] = u;
    }
    if (i < 256 * 128) {           // W1T[n][k] = W1[k][n]
        int n = i >> 7, k = i & 127;
        g_w1t[i] = __float2half_rn(W1[k * 256 + n]);
    }
    if (i < 256 * 256) {           // W2T[n][k] = W2[k][n]
        int n = i >> 8, k = i & 255;
        g_w2t[i] = __float2half_rn(W2[k * 256 + n]);
    }
}

__global__ void k_hist(const int* __restrict__ dst) {
    int e = blockIdx.x * blockDim.x + threadIdx.x;
    if (e < N_EDGES) atomicAdd(&g_count[dst[e]], 1);
}

// block-local exclusive scan + dinv; last block to finish scans the block sums
__global__ void k_scan1() {
    __shared__ int warpsums[32];
    __shared__ int s_last;
    int b = blockIdx.x;
    int i = b * SCAN_B + threadIdx.x;
    int v = (i < N_NODES) ? g_count[i] : 0;
    if (i < N_NODES) g_dinv[i] = rsqrtf((float)v + 1.0f);
    int lane = threadIdx.x & 31, w = threadIdx.x >> 5;
    int p = v;
#pragma unroll
    for (int off = 1; off < 32; off <<= 1) {
        int t = __shfl_up_sync(0xFFFFFFFFu, p, off);
        if (lane >= off) p += t;
    }
    if (lane == 31) warpsums[w] = p;
    __syncthreads();
    if (w == 0) {
        int s = warpsums[lane];
#pragma unroll
        for (int off = 1; off < 32; off <<= 1) {
            int t = __shfl_up_sync(0xFFFFFFFFu, s, off);
            if (lane >= off) s += t;
        }
        warpsums[lane] = s;
    }
    __syncthreads();
    int excl = p - v + (w > 0 ? warpsums[w - 1] : 0);
    if (i < N_NODES) g_rowptr[i] = excl;              // block-local exclusive
    if (threadIdx.x == SCAN_B - 1) g_bsum[b] = excl + v;

    __threadfence();
    __syncthreads();
    if (threadIdx.x == 0) {
        int t = atomicAdd(&g_ticket, 1);
        s_last = (t == NBLK - 1) ? 1 : 0;
    }
    __syncthreads();
    if (s_last) {
        if (threadIdx.x == 0) g_ticket = 0;           // reset for graph replay
        if (threadIdx.x < 32) {
            __threadfence();
            int l = threadIdx.x;
            int i0 = 2 * l, i1 = 2 * l + 1;
            int v0 = (i0 < NBLK) ? g_bsum[i0] : 0;
            int v1 = (i1 < NBLK) ? g_bsum[i1] : 0;
            int pr = v0 + v1;
            int s = pr;
#pragma unroll
            for (int off = 1; off < 32; off <<= 1) {
                int t = __shfl_up_sync(0xFFFFFFFFu, s, off);
                if (l >= off) s += t;
            }
            int e2 = s - pr;
            if (i0 < NBLK) g_boff[i0] = e2;
            if (i1 < NBLK) g_boff[i1] = e2 + v0;
            int total = __shfl_sync(0xFFFFFFFFu, s, 31);
            if (i0 == NBLK - 1) g_rowptr[N_NODES] = total - e2;
            if (i1 == NBLK - 1) g_rowptr[N_NODES] = total - (e2 + v0);
        }
    }
}

__global__ void k_sort(const int* __restrict__ src, const int* __restrict__ dst) {
    int e = blockIdx.x * blockDim.x + threadIdx.x;
    if (e >= N_EDGES) return;
    int d = dst[e];
    int pos = g_rowptr[d] + g_boff[d >> 10] + atomicAdd(&g_fill[d], 1);
    g_col[pos] = src[e];
}

// ---------------- gather helpers ----------------
#define H4_ACC(T, W)                                                   \
    {                                                                  \
        float2 f0 = __half22float2(*(const __half2*)&(T).x);           \
        float2 f1 = __half22float2(*(const __half2*)&(T).y);           \
        acc.x += (W) * f0.x; acc.y += (W) * f0.y;                      \
        acc.z += (W) * f1.x; acc.w += (W) * f1.y;                      \
    }

#define AGG_BODY(RS)                                                          \
    int p = beg;                                                              \
    for (; p + 7 < end; p += 8) {                                             \
        int   sx[8];                                                          \
        float wx[8];                                                          \
        uint2 tx[8];                                                          \
        _Pragma("unroll")                                                     \
        for (int q = 0; q < 8; q++) sx[q] = g_col[p + q];                     \
        _Pragma("unroll")                                                     \
        for (int q = 0; q < 8; q++) wx[q] = g_dinv[sx[q]];                    \
        _Pragma("unroll")                                                     \
        for (int q = 0; q < 8; q++) tx[q] = base[(size_t)sx[q] * (RS)];       \
        _Pragma("unroll")                                                     \
        for (int q = 0; q < 8; q++) { H4_ACC(tx[q], wx[q]); }                 \
    }                                                                         \
    for (; p < end; p++) {                                                    \
        int s = g_col[p];                                                     \
        float wv = g_dinv[s];                                                 \
        uint2 t = base[(size_t)s * (RS)];                                     \
        H4_ACC(t, wv);                                                        \
    }

#define H8A(T, W)                                                             \
    {                                                                         \
        float2 f;                                                             \
        f = __half22float2(*(const __half2*)&(T).x);                          \
        a0.x += (W) * f.x; a0.y += (W) * f.y;                                 \
        f = __half22float2(*(const __half2*)&(T).y);                          \
        a0.z += (W) * f.x; a0.w += (W) * f.y;                                 \
        f = __half22float2(*(const __half2*)&(T).z);                          \
        a1.x += (W) * f.x; a1.y += (W) * f.y;                                 \
        f = __half22float2(*(const __half2*)&(T).w);                          \
        a1.z += (W) * f.x; a1.w += (W) * f.y;                                 \
    }

// ---------------- fp16 MMA helper (m16n8k16, fp32 accum) ----------------
__device__ __forceinline__ void mma_f16(float c[4], uint32_t a0, uint32_t a1,
                                        uint32_t a2, uint32_t a3,
                                        uint32_t b0, uint32_t b1) {
    asm volatile(
        "mma.sync.aligned.m16n8k16.row.col.f32.f16.f16.f32 "
        "{%0,%1,%2,%3}, {%4,%5,%6,%7}, {%8,%9}, {%0,%1,%2,%3};"
        : "+f"(c[0]), "+f"(c[1]), "+f"(c[2]), "+f"(c[3])
        : "r"(a0), "r"(a1), "r"(a2), "r"(a3), "r"(b0), "r"(b1));
}

// ---------------- fused layer 1: agg(x16) -> GEMM1 -> h1h ----------------
// block = 128 nodes. Phase A: 8 warps x 16 nodes gather into smem A [128][136].
// Phase B: for each N-half (128 cols), load W1T half into smem, MMA, epilogue.
#define LD1 136   // halves per A/B smem row (128 + 8 pad); stride 68 words

__global__ void __launch_bounds__(256, 2)
k_fused1(const __half* __restrict__ in, const __half* __restrict__ BT,
         const float* __restrict__ bias, __half* __restrict__ C) {
    extern __shared__ __half sm1[];
    __half* As = sm1;                // [128][LD1]
    __half* Bs = sm1 + 128 * LD1;    // [128][LD1]
    const int bm = blockIdx.x * 128;
    const int tid  = threadIdx.x;
    const int lane = tid & 31;
    const int warp = tid >> 5;
    const int wm = warp >> 2;
    const int wnn = warp & 3;
    const int g   = lane >> 2;
    const int tig = lane & 3;

    // ---- phase A: gather-aggregate 16 nodes per warp ----
    for (int i = 0; i < 16; i++) {
        int ln = warp * 16 + i;
        int node = bm + ln;
        uint2 u = make_uint2(0u, 0u);
        if (node < N_NODES) {
            int beg = g_rowptr[node]     + g_boff[node >> 10];
            int end = g_rowptr[node + 1] + g_boff[(node + 1) >> 10];
            float dn = g_dinv[node];
            const uint2* base = (const uint2*)in + lane;
            float4 acc = make_float4(0.f, 0.f, 0.f, 0.f);
            AGG_BODY(32)
            uint2 t = base[(size_t)node * 32];
            float2 f0 = __half22float2(*(const __half2*)&t.x);
            float2 f1 = __half22float2(*(const __half2*)&t.y);
            __half2 h0 = __floats2half2_rn(dn * (acc.x + dn * f0.x),
                                           dn * (acc.y + dn * f0.y));
            __half2 h1 = __floats2half2_rn(dn * (acc.z + dn * f1.x),
                                           dn * (acc.w + dn * f1.y));
            u.x = *(const uint32_t*)&h0;
            u.y = *(const uint32_t*)&h1;
        }
        *(uint2*)&As[ln * LD1 + lane * 4] = u;
    }
    __syncthreads();

    // ---- phase B: two N-halves ----
    for (int h = 0; h < 2; h++) {
        // load W1T rows [h*128, h*128+128) x 128 k into Bs
#pragma unroll
        for (int i = 0; i < 8; i++) {
            int idx = i * 256 + tid;      // 0..2047 uint4s
            int row = idx >> 4;
            int c8  = (idx & 15) * 8;
            *(uint4*)&Bs[row * LD1 + c8] =
                *(const uint4*)(BT + (size_t)(h * 128 + row) * 128 + c8);
        }
        __syncthreads();

        float c[4][4][4];
#pragma unroll
        for (int a = 0; a < 4; a++)
#pragma unroll
            for (int b = 0; b < 4; b++)
#pragma unroll
                for (int r = 0; r < 4; r++) c[a][b][r] = 0.f;

#pragma unroll
        for (int t = 0; t < 4; t++) {
            int k0 = t * 32;
#pragma unroll
            for (int kk = 0; kk < 32; kk += 16) {
                uint32_t af[4][4], bf[4][2];
#pragma unroll
                for (int mt = 0; mt < 4; mt++) {
                    int mb = wm * 64 + mt * 16;
                    const __half* ar0 = &As[(mb + g) * LD1 + k0 + kk + 2 * tig];
                    const __half* ar1 = &As[(mb + g + 8) * LD1 + k0 + kk + 2 * tig];
                    af[mt][0] = *(const uint32_t*)ar0;
                    af[mt][1] = *(const uint32_t*)ar1;
                    af[mt][2] = *(const uint32_t*)(ar0 + 8);
                    af[mt][3] = *(const uint32_t*)(ar1 + 8);
                }
#pragma unroll
                for (int nt = 0; nt < 4; nt++) {
                    int nb = wnn * 32 + nt * 8;
                    const __half* br = &Bs[(nb + g) * LD1 + k0 + kk + 2 * tig];
                    bf[nt][0] = *(const uint32_t*)br;
                    bf[nt][1] = *(const uint32_t*)(br + 8);
                }
#pragma unroll
                for (int mt = 0; mt < 4; mt++)
#pragma unroll
                    for (int nt = 0; nt < 4; nt++)
                        mma_f16(c[mt][nt], af[mt][0], af[mt][1], af[mt][2],
                                af[mt][3], bf[nt][0], bf[nt][1]);
            }
        }

        // epilogue: bias + relu -> fp16
#pragma unroll
        for (int nt = 0; nt < 4; nt++) {
            int col = h * 128 + wnn * 32 + nt * 8 + tig * 2;
            float bb0 = bias[col], bb1 = bias[col + 1];
#pragma unroll
            for (int mt = 0; mt < 4; mt++) {
                int row0 = bm + wm * 64 + mt * 16 + g;
                int row1 = row0 + 8;
                if (row0 < N_NODES) {
                    float vx = fmaxf(c[mt][nt][0] + bb0, 0.f);
                    float vy = fmaxf(c[mt][nt][1] + bb1, 0.f);
                    *(__half2*)(C + (size_t)row0 * 256 + col) =
                        __floats2half2_rn(vx, vy);
                }
                if (row1 < N_NODES) {
                    float vx = fmaxf(c[mt][nt][2] + bb0, 0.f);
                    float vy = fmaxf(c[mt][nt][3] + bb1, 0.f);
                    *(__half2*)(C + (size_t)row1 * 256 + col) =
                        __floats2half2_rn(vx, vy);
                }
            }
        }
        __syncthreads();   // protect Bs before next half reload
    }
}

// ---------------- fused layer 2: agg(h1h) -> GEMM2 -> proj -> out ----------
// block = 64 nodes. Phase A: 8 warps x 8 nodes gather full 256-col rows
// (uint4/lane) into smem A [64][264]. Phase B: stream W2T k-tiles (double-
// buffered), fp16 MMA, fused relu+b2 then @Wl+bl epilogue.
#define LD2A 264   // 256 + 8 pad; stride 132 words
#define LD2B 24    // 16 + 8 pad;  stride 12 words

__global__ void __launch_bounds__(256, 2)
k_fused2(const __half* __restrict__ in, const __half* __restrict__ BT,
         const float* __restrict__ b2, const float* __restrict__ Wl,
         const float* __restrict__ bl, float* __restrict__ out) {
    extern __shared__ __half sm2[];
    __half* As = sm2;                             // [64][LD2A]
    __half* Bs = sm2 + 64 * LD2A;                 // [2][256][LD2B]
    float*  red = (float*)(sm2 + 64 * LD2A + 2 * 256 * LD2B);  // [8][64][2]
    const int bm = blockIdx.x * 64;
    const int tid  = threadIdx.x;
    const int lane = tid & 31;
    const int wp   = tid >> 5;       // warp id (also the n-slice owner)
    const int g    = lane >> 2;
    const int tig  = lane & 3;

    // ---- phase A: gather-aggregate 8 nodes per warp (full 256-col rows) ----
    for (int i = 0; i < 8; i++) {
        int ln = wp * 8 + i;
        int node = bm + ln;
        uint4 u = make_uint4(0u, 0u, 0u, 0u);
        if (node < N_NODES) {
            int beg = g_rowptr[node]     + g_boff[node >> 10];
            int end = g_rowptr[node + 1] + g_boff[(node + 1) >> 10];
            float dn = g_dinv[node];
            const uint4* base = (const uint4*)in + lane;   // 16B = 8 halves
            float4 a0 = make_float4(0.f, 0.f, 0.f, 0.f);
            float4 a1 = make_float4(0.f, 0.f, 0.f, 0.f);
            int p = beg;
            for (; p + 3 < end; p += 4) {
                int   sx[4];
                float wx[4];
                uint4 tx[4];
#pragma unroll
                for (int q = 0; q < 4; q++) sx[q] = g_col[p + q];
#pragma unroll
                for (int q = 0; q < 4; q++) wx[q] = g_dinv[sx[q]];
#pragma unroll
                for (int q = 0; q < 4; q++) tx[q] = base[(size_t)sx[q] * 32];
#pragma unroll
                for (int q = 0; q < 4; q++) { H8A(tx[q], wx[q]); }
            }
            for (; p < end; p++) {
                int s = g_col[p];
                float wv = g_dinv[s];
                uint4 t = base[(size_t)s * 32];
                H8A(t, wv);
            }
            uint4 t = base[(size_t)node * 32];
            float2 f;
            f = __half22float2(*(const __half2*)&t.x);
            __half2 h0 = __floats2half2_rn(dn * (a0.x + dn * f.x),
                                           dn * (a0.y + dn * f.y));
            f = __half22float2(*(const __half2*)&t.y);
            __half2 h1 = __floats2half2_rn(dn * (a0.z + dn * f.x),
                                           dn * (a0.w + dn * f.y));
            f = __half22float2(*(const __half2*)&t.z);
            __half2 h2 = __floats2half2_rn(dn * (a1.x + dn * f.x),
                                           dn * (a1.y + dn * f.y));
            f = __half22float2(*(const __half2*)&t.w);
            __half2 h3 = __floats2half2_rn(dn * (a1.z + dn * f.x),
                                           dn * (a1.w + dn * f.y));
            u.x = *(const uint32_t*)&h0;
            u.y = *(const uint32_t*)&h1;
            u.z = *(const uint32_t*)&h2;
            u.w = *(const uint32_t*)&h3;
        }
        *(uint4*)&As[ln * LD2A + lane * 8] = u;
    }

    // ---- phase B: B-streaming fp16 MMA over K=256 ----
    float c[4][4][4];
#pragma unroll
    for (int a = 0; a < 4; a++)
#pragma unroll
        for (int b = 0; b < 4; b++)
#pragma unroll
            for (int r = 0; r < 4; r++) c[a][b][r] = 0.f;

    uint4 ub0, ub1;
    const int b_i0 = tid;                // uint4 index 0..255
    const int b_i1 = tid + 256;
    const int b_r0 = b_i0 >> 1, b_c0 = (b_i0 & 1) * 8;
    const int b_r1 = b_i1 >> 1, b_c1 = (b_i1 & 1) * 8;

#define B2_LOAD(k0)                                                           \
    {                                                                         \
        ub0 = *(const uint4*)(BT + (size_t)b_r0 * 256 + (k0) + b_c0);         \
        ub1 = *(const uint4*)(BT + (size_t)b_r1 * 256 + (k0) + b_c1);         \
    }
#define B2_STORE(buf)                                                         \
    {                                                                         \
        *(uint4*)&Bs[(size_t)(buf) * 256 * LD2B + b_r0 * LD2B + b_c0] = ub0;  \
        *(uint4*)&Bs[(size_t)(buf) * 256 * LD2B + b_r1 * LD2B + b_c1] = ub1;  \
    }

    B2_LOAD(0);
    __syncthreads();         // As ready
    B2_STORE(0);
    __syncthreads();
#pragma unroll
    for (int t = 0; t < 16; t++) {       // 256 / BK16
        if (t + 1 < 16) B2_LOAD((t + 1) * 16);
        const int buf = t & 1;
        const int k0 = t * 16;
        uint32_t af[4][4], bf[4][2];
#pragma unroll
        for (int mt = 0; mt < 4; mt++) {
            int mb = mt * 16;
            const __half* ar0 = &As[(mb + g) * LD2A + k0 + 2 * tig];
            const __half* ar1 = &As[(mb + g + 8) * LD2A + k0 + 2 * tig];
            af[mt][0] = *(const uint32_t*)ar0;
            af[mt][1] = *(const uint32_t*)ar1;
            af[mt][2] = *(const uint32_t*)(ar0 + 8);
            af[mt][3] = *(const uint32_t*)(ar1 + 8);
        }
#pragma unroll
        for (int nt = 0; nt < 4; nt++) {
            int nb = wp * 32 + nt * 8;
            const __half* br = &Bs[(size_t)buf * 256 * LD2B + (nb + g) * LD2B + 2 * tig];
            bf[nt][0] = *(const uint32_t*)br;
            bf[nt][1] = *(const uint32_t*)(br + 8);
        }
#pragma unroll
        for (int mt = 0; mt < 4; mt++)
#pragma unroll
            for (int nt = 0; nt < 4; nt++)
                mma_f16(c[mt][nt], af[mt][0], af[mt][1], af[mt][2], af[mt][3],
                        bf[nt][0], bf[nt][1]);
        if (t + 1 < 16) B2_STORE((t + 1) & 1);
        __syncthreads();
    }
#undef B2_LOAD
#undef B2_STORE

    // ---- fused epilogue: v = relu(acc + b2); partial = v @ Wl; reduce ----
    float wl0[8], wl1[8], bb[8];
#pragma unroll
    for (int nt = 0; nt < 4; nt++)
#pragma unroll
        for (int j = 0; j < 2; j++) {
            int col = wp * 32 + nt * 8 + tig * 2 + j;
            int idx = nt * 2 + j;
            bb[idx]  = b2[col];
            wl0[idx] = Wl[col * 2 + 0];
            wl1[idx] = Wl[col * 2 + 1];
        }
#pragma unroll
    for (int mt = 0; mt < 4; mt++) {
        float r0s0 = 0.f, r0s1 = 0.f, r1s0 = 0.f, r1s1 = 0.f;
#pragma unroll
        for (int nt = 0; nt < 4; nt++) {
            float v0 = fmaxf(c[mt][nt][0] + bb[nt * 2 + 0], 0.f);
            float v1 = fmaxf(c[mt][nt][1] + bb[nt * 2 + 1], 0.f);
            float v2 = fmaxf(c[mt][nt][2] + bb[nt * 2 + 0], 0.f);
            float v3 = fmaxf(c[mt][nt][3] + bb[nt * 2 + 1], 0.f);
            r0s0 += v0 * wl0[nt * 2] + v1 * wl0[nt * 2 + 1];
            r0s1 += v0 * wl1[nt * 2] + v1 * wl1[nt * 2 + 1];
            r1s0 += v2 * wl0[nt * 2] + v3 * wl0[nt * 2 + 1];
            r1s1 += v2 * wl1[nt * 2] + v3 * wl1[nt * 2 + 1];
        }
#pragma unroll
        for (int off = 1; off <= 2; off <<= 1) {
            r0s0 += __shfl_xor_sync(0xFFFFFFFFu, r0s0, off);
            r0s1 += __shfl_xor_sync(0xFFFFFFFFu, r0s1, off);
            r1s0 += __shfl_xor_sync(0xFFFFFFFFu, r1s0, off);
            r1s1 += __shfl_xor_sync(0xFFFFFFFFu, r1s1, off);
        }
        if (tig == 0) {
            red[(wp * 64 + mt * 16 + g) * 2 + 0]     = r0s0;
            red[(wp * 64 + mt * 16 + g) * 2 + 1]     = r0s1;
            red[(wp * 64 + mt * 16 + 8 + g) * 2 + 0] = r1s0;
            red[(wp * 64 + mt * 16 + 8 + g) * 2 + 1] = r1s1;
        }
    }
    __syncthreads();
    if (tid < 128) {
        int row = tid >> 1, d = tid & 1;
        float s = bl[d];
#pragma unroll
        for (int w = 0; w < 8; w++) s += red[(w * 64 + row) * 2 + d];
        int r = bm + row;
        if (r < N_NODES) out[(size_t)r * 2 + d] = s;
    }
}

// ---------------- launch ----------------
#define SMEM1 (2 * 128 * LD1 * 2)                                  // 69632 B
#define SMEM2 ((64 * LD2A + 2 * 256 * LD2B) * 2 + 8 * 64 * 2 * 4)  // 62464 B

extern "C" void kernel_launch(void* const* d_in, const int* in_sizes, int n_in,
                              void* d_out, int out_size) {
    const float* x   = (const float*)d_in[0];
    const int*   ei  = (const int*)d_in[1];
    const float* W1  = (const float*)d_in[2];
    const float* b1  = (const float*)d_in[3];
    const float* W2  = (const float*)d_in[4];
    const float* b2  = (const float*)d_in[5];
    const float* Wl  = (const float*)d_in[6];
    const float* bl  = (const float*)d_in[7];
    float* out = (float*)d_out;

    const int* src = ei;            // edge_index[0, :]
    const int* dst = ei + N_EDGES;  // edge_index[1, :]

    __half* x16;   cudaGetSymbolAddress((void**)&x16,   g_x16);
    __half* w1t;   cudaGetSymbolAddress((void**)&w1t,   g_w1t);
    __half* w2t;   cudaGetSymbolAddress((void**)&w2t,   g_w2t);
    __half* h1h;   cudaGetSymbolAddress((void**)&h1h,   g_h1h);

    cudaFuncSetAttribute(k_fused1, cudaFuncAttributeMaxDynamicSharedMemorySize,
                         SMEM1);
    cudaFuncSetAttribute(k_fused2, cudaFuncAttributeMaxDynamicSharedMemorySize,
                         SMEM2);

    const int TB = 256;
    k_init<<<(N_NODES * IN_DIM / 4 + TB - 1) / TB, TB>>>(x, W1, W2);
    k_hist<<<(N_EDGES + TB - 1) / TB, TB>>>(dst);
    k_scan1<<<NBLK, SCAN_B>>>();
    k_sort<<<(N_EDGES + TB - 1) / TB, TB>>>(src, dst);

    // fused layer 1: agg + GEMM1 (+bias+relu) -> h1h
    {
        int blocks = (N_NODES + 127) / 128;
        k_fused1<<<blocks, 256, SMEM1>>>(x16, w1t, b1, h1h);
    }
    // fused layer 2: agg + GEMM2 (+bias+relu) + 256->2 projection -> out
    {
        int blocks = (N_NODES + 63) / 64;
        k_fused2<<<blocks, 256, SMEM2>>>(h1h, w2t, b2, Wl, bl, out);
    }
}